// round 15
// baseline (speedup 1.0000x reference)
#include <cuda_runtime.h>
#include <cuda_fp16.h>
#include <cstdint>

#define NNODES 20000
#define NEDGES 320000
#define DIM    256
#define KSEL   4096

#define BM 128
#define BN 128
#define BK 32                       // K halves per pipeline stage
#define SPADH 40                    // smem row stride in halves (80B, conflict-free)
#define STAGES 4
#define STAGE_BYTES ((BM + BN) * SPADH * 2)      // 20480 B / stage
#define GEMM_SMEM (STAGES * STAGE_BYTES)         // 81920 B
#define GTHREADS 512

// ---------------- device scratch ----------------
__device__ float  g_sup512[NNODES * 512];  // suph | axs | ahs (all half)
__device__ float  g_agg[NNODES * DIM];     // h as half
__device__ __half g_xh[NNODES * DIM];      // X as half
__device__ __half g_s[KSEL * DIM];         // s as half (Gram input)
__device__ __half g_wt[3 * DIM * DIM];     // [W1t | Wsdt | W2t] half
__device__ int    g_rowptr[NNODES + 1];
__device__ int    g_cnt[NNODES];
__device__ int    g_ecol[NEDGES];
__device__ float  g_ew[NEDGES];
__device__ int    g_idx[KSEL];

// ---------------- helpers ----------------
__device__ __forceinline__ int block_excl_scan_1024(int v) {
    __shared__ int wsum[32];
    int lane = threadIdx.x & 31;
    int wid  = threadIdx.x >> 5;
    int x = v;
#pragma unroll
    for (int o = 1; o < 32; o <<= 1) {
        int y = __shfl_up_sync(0xFFFFFFFFu, x, o);
        if (lane >= o) x += y;
    }
    if (lane == 31) wsum[wid] = x;
    __syncthreads();
    if (wid == 0) {
        int w = wsum[lane];
        int xx = w;
#pragma unroll
        for (int o = 1; o < 32; o <<= 1) {
            int y = __shfl_up_sync(0xFFFFFFFFu, xx, o);
            if (lane >= o) xx += y;
        }
        wsum[lane] = xx - w;
    }
    __syncthreads();
    return (x - v) + wsum[wid];
}

__device__ __forceinline__ uint32_t sptr(const void* p) {
    return (uint32_t)__cvta_generic_to_shared(p);
}
__device__ __forceinline__ void ldsm4(uint32_t* r, uint32_t addr) {
    asm volatile("ldmatrix.sync.aligned.m8n8.x4.shared.b16 {%0,%1,%2,%3}, [%4];"
                 : "=r"(r[0]), "=r"(r[1]), "=r"(r[2]), "=r"(r[3]) : "r"(addr));
}
__device__ __forceinline__ void mma_f16(float* c, const uint32_t* a,
                                        uint32_t b0, uint32_t b1) {
    asm volatile(
        "mma.sync.aligned.m16n8k16.row.col.f32.f16.f16.f32 "
        "{%0,%1,%2,%3},{%4,%5,%6,%7},{%8,%9},{%0,%1,%2,%3};"
        : "+f"(c[0]), "+f"(c[1]), "+f"(c[2]), "+f"(c[3])
        : "r"(a[0]), "r"(a[1]), "r"(a[2]), "r"(a[3]), "r"(b0), "r"(b1));
}
__device__ __forceinline__ void cpa16(uint32_t saddr, const void* g, bool pred) {
    int sz = pred ? 16 : 0;
    asm volatile("cp.async.ca.shared.global [%0], [%1], 16, %2;"
                 :: "r"(saddr), "l"(g), "r"(sz));
}
__device__ __forceinline__ void cpa_commit() {
    asm volatile("cp.async.commit_group;");
}
template <int N>
__device__ __forceinline__ void cpa_wait() {
    asm volatile("cp.async.wait_group %0;" :: "n"(N));
}

// ---------------- CSR build ----------------
__global__ void k_zero_cnt() {
    int i = blockIdx.x * blockDim.x + threadIdx.x;
    if (i < NNODES) g_cnt[i] = 0;
}
__global__ void k_hist(const int* __restrict__ row) {
    int e = blockIdx.x * blockDim.x + threadIdx.x;
    if (e < NEDGES) atomicAdd(&g_cnt[row[e]], 1);
}
__global__ void k_scan_idx(const int* __restrict__ labels) {
    const int CH = (NNODES + 1023) / 1024;
    int t = threadIdx.x;
    int start = t * CH;
    int end = min(start + CH, NNODES);
    {
        int s = 0;
        for (int i = start; i < end; i++) s += g_cnt[i];
        int off = block_excl_scan_1024(s);
        int run = off;
        for (int i = start; i < end; i++) {
            int c = g_cnt[i];
            g_rowptr[i] = run;
            run += c;
            g_cnt[i] = 0;
        }
        if (t == 1023) g_rowptr[NNODES] = run;
    }
    __syncthreads();
    {
        int s = 0;
        for (int i = start; i < end; i++) s += (labels[i] == 1);
        int off = block_excl_scan_1024(s);
        for (int i = start; i < end; i++)
            if (labels[i] == 1) g_idx[off++] = i;
    }
}
__global__ void k_scatter(const int* __restrict__ row, const int* __restrict__ col,
                          const float* __restrict__ w) {
    int e = blockIdx.x * blockDim.x + threadIdx.x;
    if (e < NEDGES) {
        int r = row[e];
        int p = g_rowptr[r] + atomicAdd(&g_cnt[r], 1);
        g_ecol[p] = col[e];
        g_ew[p]   = w[e];
    }
}

// -------- merged preproc: transpose weights -> half; X -> xh (half) ----------------
__global__ void __launch_bounds__(256) k_preproc(
    const float* __restrict__ X, const float* __restrict__ W0,
    const float* __restrict__ W1, const float* __restrict__ W2)
{
    int b = blockIdx.x;
    if (b < 192) {
        __shared__ float t[32][33];
        int z = b >> 6, r = b & 63;
        const float* W = (z == 0) ? W0 : (z == 1) ? W1 : W2;
        __half* Wt = g_wt + (size_t)z * DIM * DIM;
        int bx = (r & 7) * 32, by = (r >> 3) * 32;
        int x = threadIdx.x & 31, y = threadIdx.x >> 5;
        for (int dy = 0; dy < 32; dy += 8)
            t[y + dy][x] = W[(by + y + dy) * DIM + bx + x];
        __syncthreads();
        for (int dy = 0; dy < 32; dy += 8)
            Wt[(bx + y + dy) * DIM + by + x] = __float2half_rn(t[x][y + dy]);
    } else {
        int i = (b - 192) * 256 + threadIdx.x;            // float4 index
        float4 v = ((const float4*)X)[i];
        __half2 h0 = __floats2half2_rn(v.x, v.y);
        __half2 h1 = __floats2half2_rn(v.z, v.w);
        uint2 u;
        u.x = *(uint32_t*)&h0; u.y = *(uint32_t*)&h1;
        ((uint2*)g_xh)[i] = u;
    }
}

// ---------------- FP16 TC GEMM NT (512 threads, warp tile 32x32) -------------------
// C[M,ldc] = A[M,256] @ Bt[N,256]^T  (A,Bt half; accum fp32)
// epilogue: += bias (if non-null); Ch non-null -> write half, else float to C.
template <bool SYM>
__global__ void __launch_bounds__(GTHREADS) k_gemm_tc(
    const __half* __restrict__ A, const __half* __restrict__ Bt,
    float* __restrict__ C, int M, int ldc,
    const float* __restrict__ bias, __half* __restrict__ Ch)
{
    extern __shared__ float smf[];
    const int tid = threadIdx.x;
    const int warp = tid >> 5, lane = tid & 31;

    int bm, bn;
    if (SYM) {
        int t = blockIdx.x;
        int i = (int)((sqrtf(8.f * t + 1.f) - 1.f) * 0.5f);
        while ((i + 1) * (i + 2) / 2 <= t) i++;
        while (i * (i + 1) / 2 > t) i--;
        int j = t - i * (i + 1) / 2;
        bm = i * BM; bn = j * BN;
    } else {
        bm = blockIdx.y * BM; bn = blockIdx.x * BN;
    }
    const bool diag = SYM && (bm == bn);
    const int wm = (warp >> 2) * 32;         // 4 warps along M
    const int wn = (warp & 3) * 32;          // 4 warps along N

    // staging role: ar in 0..255 covers A rows (0-127) then B rows (128-255)
    const int ar = tid >> 1;
    const int su = tid & 1;                  // 16-half (32B) segment of 32-half row
    const bool isA = ar < BM;
    const __half* gp = isA ? A + (size_t)(bm + ar) * DIM + su * 16
                           : Bt + (size_t)(bn + (ar - BM)) * DIM + su * 16;
    const bool ld_ok = isA ? (SYM || (bm + ar) < M) : (!diag);
    const uint32_t smbase = sptr(smf);
    const uint32_t s_off = smbase + (uint32_t)(ar * SPADH + su * 16) * 2;

    const int lrow = lane & 15;
    const int lkh  = lane >> 4;

    float c[2][4][4];
#pragma unroll
    for (int i = 0; i < 2; i++)
#pragma unroll
        for (int j = 0; j < 4; j++)
#pragma unroll
            for (int q = 0; q < 4; q++) c[i][j][q] = 0.f;

    const int NT = DIM / BK;   // 8

#pragma unroll
    for (int s = 0; s < STAGES - 1; s++) {
        const int k0 = s * BK;
        const uint32_t so = (uint32_t)(s * STAGE_BYTES);
        cpa16(s_off + so,      gp + k0,     ld_ok);
        cpa16(s_off + so + 16, gp + k0 + 8, ld_ok);
        cpa_commit();
    }

#pragma unroll 1
    for (int t = 0; t < NT; t++) {
        cpa_wait<STAGES - 2>();
        __syncthreads();

        const int kt = t + STAGES - 1;
        if (kt < NT) {
            const int k0 = kt * BK;
            const uint32_t so = (uint32_t)((kt & (STAGES - 1)) * STAGE_BYTES);
            cpa16(s_off + so,      gp + k0,     ld_ok);
            cpa16(s_off + so + 16, gp + k0 + 8, ld_ok);
        }
        cpa_commit();

        const int st = t & (STAGES - 1);
        const uint32_t soA = smbase + (uint32_t)(st * STAGE_BYTES);
        const uint32_t soB = diag ? soA : soA + BM * SPADH * 2;
#pragma unroll
        for (int kk = 0; kk < 2; kk++) {           // two k16 steps per BK=32
            const uint32_t kb = (uint32_t)(kk * 32 + lkh * 16);   // bytes
            uint32_t a[2][4], b[2][4];
#pragma unroll
            for (int mi = 0; mi < 2; mi++)
                ldsm4(a[mi], soA + (uint32_t)((wm + mi * 16 + lrow) * SPADH) * 2 + kb);
#pragma unroll
            for (int nj = 0; nj < 2; nj++)
                ldsm4(b[nj], soB + (uint32_t)((wn + nj * 16 + lrow) * SPADH) * 2 + kb);
#pragma unroll
            for (int mi = 0; mi < 2; mi++)
#pragma unroll
                for (int nj4 = 0; nj4 < 4; nj4++) {
                    const int grp = nj4 >> 1, sel = nj4 & 1;
                    mma_f16(c[mi][nj4], a[mi], b[grp][sel], b[grp][sel + 2]);
                }
        }
    }

    const int g = lane >> 2, tg = lane & 3;
    if (!SYM) {
#pragma unroll
        for (int mi = 0; mi < 2; mi++)
#pragma unroll
            for (int nj = 0; nj < 4; nj++) {
                int m0 = bm + wm + mi * 16 + g;
                int n0 = bn + wn + nj * 8 + tg * 2;
                float v0 = c[mi][nj][0], v1 = c[mi][nj][1];
                float v2 = c[mi][nj][2], v3 = c[mi][nj][3];
                if (bias) {
                    float b0 = __ldg(&bias[n0]), b1 = __ldg(&bias[n0 + 1]);
                    v0 += b0; v1 += b1; v2 += b0; v3 += b1;
                }
                if (Ch) {
                    __half2 h0 = __floats2half2_rn(v0, v1);
                    __half2 h1 = __floats2half2_rn(v2, v3);
                    if (m0 < M)
                        *(__half2*)(Ch + (size_t)m0 * ldc + n0) = h0;
                    if (m0 + 8 < M)
                        *(__half2*)(Ch + (size_t)(m0 + 8) * ldc + n0) = h1;
                } else {
                    if (m0 < M)
                        *(float2*)&C[(size_t)m0 * ldc + n0] = make_float2(v0, v1);
                    if (m0 + 8 < M)
                        *(float2*)&C[(size_t)(m0 + 8) * ldc + n0] = make_float2(v2, v3);
                }
            }
    } else {
        cpa_wait<0>();
        __syncthreads();
        const int LD = 129;
#pragma unroll
        for (int mi = 0; mi < 2; mi++)
#pragma unroll
            for (int nj = 0; nj < 4; nj++) {
                int r0 = wm + mi * 16 + g;
                int c0 = wn + nj * 8 + tg * 2;
                smf[r0 * LD + c0]       = c[mi][nj][0];
                smf[r0 * LD + c0 + 1]   = c[mi][nj][1];
                smf[(r0 + 8) * LD + c0]     = c[mi][nj][2];
                smf[(r0 + 8) * LD + c0 + 1] = c[mi][nj][3];
            }
        __syncthreads();
#pragma unroll
        for (int it = 0; it < 8; it++) {
            int idx = it * GTHREADS + tid;     // 4096 float4s
            int r = idx >> 5, c4 = (idx & 31) * 4;
            float4 v = make_float4(smf[r * LD + c4], smf[r * LD + c4 + 1],
                                   smf[r * LD + c4 + 2], smf[r * LD + c4 + 3]);
            *(float4*)&C[(size_t)(bm + r) * ldc + bn + c4] = v;
        }
        if (bm != bn) {
#pragma unroll 4
            for (int it = 0; it < 32; it++) {
                int idx = it * GTHREADS + tid; // 16384 floats
                int r = idx >> 7, cc = idx & 127;
                C[(size_t)(bn + r) * ldc + bm + cc] = smf[cc * LD + r];
            }
        }
    }
}

// ------------- vectorized SpMM: 4 edge-lanes x 64 col-lanes (half in/out) ----------
template <bool RELU>
__global__ void __launch_bounds__(256) k_spmm_v4(
    const __half* __restrict__ sup,
    const float4* __restrict__ bias, __half* __restrict__ out,
    const int* __restrict__ rows)
{
    __shared__ int   sc[32];
    __shared__ float sw[32];
    __shared__ float4 red[3][64];
    const int tid = threadIdx.x;
    const int j4 = tid & 63;
    const int el = tid >> 6;
    const int b = blockIdx.x;
    const int r = rows ? rows[b] : b;
    const int beg = g_rowptr[r];
    const int deg = g_rowptr[r + 1] - beg;

    float4 acc = make_float4(0.f, 0.f, 0.f, 0.f);
    for (int base = 0; base < deg; base += 32) {
        int m = min(32, deg - base);
        if (tid < m) {
            sc[tid] = g_ecol[beg + base + tid];
            sw[tid] = g_ew[beg + base + tid];
        }
        __syncthreads();
        for (int e = el; e < m; e += 4) {
            float w = sw[e];
            uint2 u = ((const uint2*)sup)[(size_t)sc[e] * 64 + j4];
            float2 f0 = __half22float2(*(__half2*)&u.x);
            float2 f1 = __half22float2(*(__half2*)&u.y);
            acc.x += w * f0.x; acc.y += w * f0.y;
            acc.z += w * f1.x; acc.w += w * f1.y;
        }
        __syncthreads();
    }
    if (el > 0) red[el - 1][j4] = acc;
    __syncthreads();
    if (el == 0) {
        float4 r0 = red[0][j4], r1 = red[1][j4], r2 = red[2][j4];
        acc.x += r0.x + r1.x + r2.x;
        acc.y += r0.y + r1.y + r2.y;
        acc.z += r0.z + r1.z + r2.z;
        acc.w += r0.w + r1.w + r2.w;
        if (bias) {
            float4 b4 = bias[j4];
            acc.x += b4.x; acc.y += b4.y; acc.z += b4.z; acc.w += b4.w;
        }
        if (RELU) {
            acc.x = fmaxf(acc.x, 0.f); acc.y = fmaxf(acc.y, 0.f);
            acc.z = fmaxf(acc.z, 0.f); acc.w = fmaxf(acc.w, 0.f);
        }
        __half2 h0 = __floats2half2_rn(acc.x, acc.y);
        __half2 h1 = __floats2half2_rn(acc.z, acc.w);
        uint2 u; u.x = *(uint32_t*)&h0; u.y = *(uint32_t*)&h1;
        ((uint2*)out)[(size_t)b * 64 + j4] = u;
    }
}

// ---------------- launch ----------------
extern "C" void kernel_launch(void* const* d_in, const int* in_sizes, int n_in,
                              void* d_out, int out_size) {
    const float* X      = (const float*)d_in[0];
    const int*   erow   = (const int*)d_in[1];
    const int*   ecol   = (const int*)d_in[2];
    const float* ew     = (const float*)d_in[3];
    const int*   labels = (const int*)d_in[4];
    const float* W1     = (const float*)d_in[5];
    const float* b1     = (const float*)d_in[6];
    const float* W2     = (const float*)d_in[7];
    const float* b2     = (const float*)d_in[8];
    const float* Wsd    = (const float*)d_in[9];
    const float* bsd    = (const float*)d_in[10];
    float* out = (float*)d_out;

    void *p_sup512, *p_agg, *p_xh, *p_s, *p_wt, *p_idx;
    cudaGetSymbolAddress(&p_sup512, g_sup512);
    cudaGetSymbolAddress(&p_agg, g_agg);
    cudaGetSymbolAddress(&p_xh, g_xh);
    cudaGetSymbolAddress(&p_s, g_s);
    cudaGetSymbolAddress(&p_wt, g_wt);
    cudaGetSymbolAddress(&p_idx, g_idx);
    __half* suph = (__half*)p_sup512;                       // [20000,256]
    __half* axs  = suph + (size_t)NNODES * DIM;             // [4096,256]
    __half* ahs  = axs + (size_t)KSEL * DIM;                // [4096,256]
    __half* h    = (__half*)p_agg;                          // [20000,256]
    __half* xh   = (__half*)p_xh;
    __half* sbuf = (__half*)p_s;                            // [4096,256]
    __half* wt1  = (__half*)p_wt;
    __half* wtsd = (__half*)p_wt + DIM * DIM;
    __half* wt2  = (__half*)p_wt + 2 * DIM * DIM;
    const int* idxp = (const int*)p_idx;

    static cudaStream_t sB = nullptr;
    static cudaEvent_t evFork, evPre, evCsr, evGram;
    if (!sB) {
        cudaFuncSetAttribute(k_gemm_tc<false>,
                             cudaFuncAttributeMaxDynamicSharedMemorySize, GEMM_SMEM);
        cudaFuncSetAttribute(k_gemm_tc<true>,
                             cudaFuncAttributeMaxDynamicSharedMemorySize, GEMM_SMEM);
        cudaStreamCreateWithFlags(&sB, cudaStreamNonBlocking);
        cudaEventCreateWithFlags(&evFork, cudaEventDisableTiming);
        cudaEventCreateWithFlags(&evPre, cudaEventDisableTiming);
        cudaEventCreateWithFlags(&evCsr, cudaEventDisableTiming);
        cudaEventCreateWithFlags(&evGram, cudaEventDisableTiming);
    }

    dim3 g1(DIM / BN, (NNODES + BM - 1) / BM);       // (2, 157)
    dim3 gSmall(DIM / BN, KSEL / BM);                // (2, 32)
    const int gramTiles = (KSEL / BM) * (KSEL / BM + 1) / 2;   // 528

    // fork B at entry: CSR build
    cudaEventRecord(evFork, 0);
    cudaStreamWaitEvent(sB, evFork, 0);

    // --- A: preproc (launch 1) ---
    k_preproc<<<192 + NNODES * DIM / 4 / 256, 256>>>(X, W1, Wsd, W2);
    cudaEventRecord(evPre, 0);

    k_zero_cnt<<<(NNODES + 255) / 256, 256, 0, sB>>>();
    k_hist<<<(NEDGES + 255) / 256, 256, 0, sB>>>(erow);

    // --- A: GEMM1 [20000,256] = xh @ W1t -> suph (launch 4 -> profiled slot) ---
    k_gemm_tc<false><<<g1, GTHREADS, GEMM_SMEM>>>(xh, wt1, nullptr, NNODES, DIM,
                                                  nullptr, suph);

    k_scan_idx<<<1, 1024, 0, sB>>>(labels);
    k_scatter<<<(NEDGES + 255) / 256, 256, 0, sB>>>(erow, ecol, ew);
    cudaEventRecord(evCsr, sB);

    // --- B: structure chain (CSR + xh) ---
    cudaStreamWaitEvent(sB, evPre, 0);
    k_spmm_v4<false><<<KSEL, 256, 0, sB>>>(xh, nullptr, axs, idxp);    // AggX[idx]
    k_gemm_tc<false><<<gSmall, GTHREADS, GEMM_SMEM, sB>>>(
        axs, wtsd, nullptr, KSEL, DIM, bsd, sbuf);                     // s (half)
    k_gemm_tc<true><<<gramTiles, GTHREADS, GEMM_SMEM, sB>>>(
        sbuf, sbuf, out + (size_t)KSEL * DIM, KSEL, KSEL, nullptr, nullptr);
    cudaEventRecord(evGram, sB);

    // --- A: attr chain ---
    cudaStreamWaitEvent(0, evCsr, 0);
    k_spmm_v4<true><<<NNODES, 256>>>(suph, (const float4*)b1, h, nullptr);
    k_spmm_v4<false><<<KSEL, 256>>>(h, nullptr, ahs, idxp);            // AggH[idx]
    k_gemm_tc<false><<<gSmall, GTHREADS, GEMM_SMEM>>>(
        ahs, wt2, out, KSEL, DIM, b2, nullptr);                        // attr out

    cudaStreamWaitEvent(0, evGram, 0);
}

// round 16
// speedup vs baseline: 1.2173x; 1.2173x over previous
#include <cuda_runtime.h>
#include <cuda_fp16.h>
#include <cstdint>

#define NNODES 20000
#define NEDGES 320000
#define DIM    256
#define KSEL   4096

#define BM 128
#define BN 128
#define BK 32                       // K halves per pipeline stage
#define SPADH 40                    // smem row stride in halves (80B, conflict-free)
#define STAGES 4
#define STAGE_BYTES ((BM + BN) * SPADH * 2)      // 20480 B / stage
#define GEMM_SMEM (STAGES * STAGE_BYTES)         // 81920 B

// ---------------- device scratch ----------------
__device__ float  g_sup512[NNODES * 512];  // suph | axs | ahs (all half)
__device__ float  g_agg[NNODES * DIM];     // h as half
__device__ __half g_xh[NNODES * DIM];      // X as half
__device__ __half g_s[KSEL * DIM];         // s as half (Gram input)
__device__ __half g_wt[3 * DIM * DIM];     // [W1t | Wsdt | W2t] half
__device__ int    g_rowptr[NNODES + 1];
__device__ int    g_cnt[NNODES];
__device__ int    g_ecol[NEDGES];
__device__ float  g_ew[NEDGES];
__device__ int    g_idx[KSEL];

// ---------------- helpers ----------------
__device__ __forceinline__ int block_excl_scan_1024(int v) {
    __shared__ int wsum[32];
    int lane = threadIdx.x & 31;
    int wid  = threadIdx.x >> 5;
    int x = v;
#pragma unroll
    for (int o = 1; o < 32; o <<= 1) {
        int y = __shfl_up_sync(0xFFFFFFFFu, x, o);
        if (lane >= o) x += y;
    }
    if (lane == 31) wsum[wid] = x;
    __syncthreads();
    if (wid == 0) {
        int w = wsum[lane];
        int xx = w;
#pragma unroll
        for (int o = 1; o < 32; o <<= 1) {
            int y = __shfl_up_sync(0xFFFFFFFFu, xx, o);
            if (lane >= o) xx += y;
        }
        wsum[lane] = xx - w;
    }
    __syncthreads();
    return (x - v) + wsum[wid];
}

__device__ __forceinline__ uint32_t sptr(const void* p) {
    return (uint32_t)__cvta_generic_to_shared(p);
}
__device__ __forceinline__ void ldsm4(uint32_t* r, uint32_t addr) {
    asm volatile("ldmatrix.sync.aligned.m8n8.x4.shared.b16 {%0,%1,%2,%3}, [%4];"
                 : "=r"(r[0]), "=r"(r[1]), "=r"(r[2]), "=r"(r[3]) : "r"(addr));
}
__device__ __forceinline__ void mma_f16(float* c, const uint32_t* a,
                                        uint32_t b0, uint32_t b1) {
    asm volatile(
        "mma.sync.aligned.m16n8k16.row.col.f32.f16.f16.f32 "
        "{%0,%1,%2,%3},{%4,%5,%6,%7},{%8,%9},{%0,%1,%2,%3};"
        : "+f"(c[0]), "+f"(c[1]), "+f"(c[2]), "+f"(c[3])
        : "r"(a[0]), "r"(a[1]), "r"(a[2]), "r"(a[3]), "r"(b0), "r"(b1));
}
__device__ __forceinline__ void cpa16(uint32_t saddr, const void* g, bool pred) {
    int sz = pred ? 16 : 0;
    asm volatile("cp.async.ca.shared.global [%0], [%1], 16, %2;"
                 :: "r"(saddr), "l"(g), "r"(sz));
}
__device__ __forceinline__ void cpa_commit() {
    asm volatile("cp.async.commit_group;");
}
template <int N>
__device__ __forceinline__ void cpa_wait() {
    asm volatile("cp.async.wait_group %0;" :: "n"(N));
}

// ---------------- CSR build ----------------
__global__ void k_zero_cnt() {
    int i = blockIdx.x * blockDim.x + threadIdx.x;
    if (i < NNODES) g_cnt[i] = 0;
}
__global__ void k_hist(const int* __restrict__ row) {
    int e = blockIdx.x * blockDim.x + threadIdx.x;
    if (e < NEDGES) atomicAdd(&g_cnt[row[e]], 1);
}
__global__ void k_scan_idx(const int* __restrict__ labels) {
    const int CH = (NNODES + 1023) / 1024;
    int t = threadIdx.x;
    int start = t * CH;
    int end = min(start + CH, NNODES);
    {
        int s = 0;
        for (int i = start; i < end; i++) s += g_cnt[i];
        int off = block_excl_scan_1024(s);
        int run = off;
        for (int i = start; i < end; i++) {
            int c = g_cnt[i];
            g_rowptr[i] = run;
            run += c;
            g_cnt[i] = 0;
        }
        if (t == 1023) g_rowptr[NNODES] = run;
    }
    __syncthreads();
    {
        int s = 0;
        for (int i = start; i < end; i++) s += (labels[i] == 1);
        int off = block_excl_scan_1024(s);
        for (int i = start; i < end; i++)
            if (labels[i] == 1) g_idx[off++] = i;
    }
}
__global__ void k_scatter(const int* __restrict__ row, const int* __restrict__ col,
                          const float* __restrict__ w) {
    int e = blockIdx.x * blockDim.x + threadIdx.x;
    if (e < NEDGES) {
        int r = row[e];
        int p = g_rowptr[r] + atomicAdd(&g_cnt[r], 1);
        g_ecol[p] = col[e];
        g_ew[p]   = w[e];
    }
}

// -------- merged preproc: transpose weights -> half; X -> xh (half) ----------------
__global__ void __launch_bounds__(256) k_preproc(
    const float* __restrict__ X, const float* __restrict__ W0,
    const float* __restrict__ W1, const float* __restrict__ W2)
{
    int b = blockIdx.x;
    if (b < 192) {
        __shared__ float t[32][33];
        int z = b >> 6, r = b & 63;
        const float* W = (z == 0) ? W0 : (z == 1) ? W1 : W2;
        __half* Wt = g_wt + (size_t)z * DIM * DIM;
        int bx = (r & 7) * 32, by = (r >> 3) * 32;
        int x = threadIdx.x & 31, y = threadIdx.x >> 5;
        for (int dy = 0; dy < 32; dy += 8)
            t[y + dy][x] = W[(by + y + dy) * DIM + bx + x];
        __syncthreads();
        for (int dy = 0; dy < 32; dy += 8)
            Wt[(bx + y + dy) * DIM + by + x] = __float2half_rn(t[x][y + dy]);
    } else {
        int i = (b - 192) * 256 + threadIdx.x;            // float4 index
        float4 v = ((const float4*)X)[i];
        __half2 h0 = __floats2half2_rn(v.x, v.y);
        __half2 h1 = __floats2half2_rn(v.z, v.w);
        uint2 u;
        u.x = *(uint32_t*)&h0; u.y = *(uint32_t*)&h1;
        ((uint2*)g_xh)[i] = u;
    }
}

// ---------------- FP16 TC GEMM NT (R13 geometry: 256 thr, warp tile 32x64) ---------
// C[M,ldc] = A[M,256] @ Bt[N,256]^T  (A,Bt half; accum fp32)
// epilogue: += bias (if non-null); Ch non-null -> write half, else float to C.
template <bool SYM>
__global__ void __launch_bounds__(256) k_gemm_tc(
    const __half* __restrict__ A, const __half* __restrict__ Bt,
    float* __restrict__ C, int M, int ldc,
    const float* __restrict__ bias, __half* __restrict__ Ch)
{
    extern __shared__ float smf[];
    const int tid = threadIdx.x;
    const int warp = tid >> 5, lane = tid & 31;

    int bm, bn;
    if (SYM) {
        int t = blockIdx.x;
        int i = (int)((sqrtf(8.f * t + 1.f) - 1.f) * 0.5f);
        while ((i + 1) * (i + 2) / 2 <= t) i++;
        while (i * (i + 1) / 2 > t) i--;
        int j = t - i * (i + 1) / 2;
        bm = i * BM; bn = j * BN;
    } else {
        bm = blockIdx.y * BM; bn = blockIdx.x * BN;
    }
    const bool diag = SYM && (bm == bn);
    const int wm = (warp >> 1) * 32;
    const int wn = (warp & 1) * 64;

    const int sr = tid >> 1;
    const int su = tid & 1;                  // 16-half (32B) segment of 32-half row
    const bool a_ok = SYM || (bm + sr) < M;
    const __half* Ap = A + (size_t)(bm + sr) * DIM + su * 16;
    const __half* Bp = Bt + (size_t)(bn + sr) * DIM + su * 16;
    const uint32_t smbase = sptr(smf);
    const uint32_t sa_base = smbase + (uint32_t)(sr * SPADH + su * 16) * 2;
    const uint32_t sb_base = sa_base + BM * SPADH * 2;

    const int lrow = lane & 15;
    const int lkh  = lane >> 4;

    float c[2][8][4];
#pragma unroll
    for (int i = 0; i < 2; i++)
#pragma unroll
        for (int j = 0; j < 8; j++)
#pragma unroll
            for (int q = 0; q < 4; q++) c[i][j][q] = 0.f;

    const int NT = DIM / BK;   // 8

#pragma unroll
    for (int s = 0; s < STAGES - 1; s++) {
        const int k0 = s * BK;
        const uint32_t so = (uint32_t)(s * STAGE_BYTES);
        cpa16(sa_base + so,      Ap + k0,     a_ok);
        cpa16(sa_base + so + 16, Ap + k0 + 8, a_ok);
        if (!diag) {
            cpa16(sb_base + so,      Bp + k0,     true);
            cpa16(sb_base + so + 16, Bp + k0 + 8, true);
        }
        cpa_commit();
    }

#pragma unroll 1
    for (int t = 0; t < NT; t++) {
        cpa_wait<STAGES - 2>();
        __syncthreads();

        const int kt = t + STAGES - 1;
        if (kt < NT) {
            const int k0 = kt * BK;
            const uint32_t so = (uint32_t)((kt & (STAGES - 1)) * STAGE_BYTES);
            cpa16(sa_base + so,      Ap + k0,     a_ok);
            cpa16(sa_base + so + 16, Ap + k0 + 8, a_ok);
            if (!diag) {
                cpa16(sb_base + so,      Bp + k0,     true);
                cpa16(sb_base + so + 16, Bp + k0 + 8, true);
            }
        }
        cpa_commit();

        const int st = t & (STAGES - 1);
        const uint32_t soA = smbase + (uint32_t)(st * STAGE_BYTES);
        const uint32_t soB = diag ? soA : soA + BM * SPADH * 2;
#pragma unroll
        for (int kk = 0; kk < 2; kk++) {           // two k16 steps per BK=32
            const uint32_t kb = (uint32_t)(kk * 32 + lkh * 16);   // bytes
            uint32_t a[2][4], b[4][4];
#pragma unroll
            for (int mi = 0; mi < 2; mi++)
                ldsm4(a[mi], soA + (uint32_t)((wm + mi * 16 + lrow) * SPADH) * 2 + kb);
#pragma unroll
            for (int nj = 0; nj < 4; nj++)
                ldsm4(b[nj], soB + (uint32_t)((wn + nj * 16 + lrow) * SPADH) * 2 + kb);
#pragma unroll
            for (int mi = 0; mi < 2; mi++)
#pragma unroll
                for (int nj8 = 0; nj8 < 8; nj8++) {
                    const int grp = nj8 >> 1, sel = nj8 & 1;
                    mma_f16(c[mi][nj8], a[mi], b[grp][sel], b[grp][sel + 2]);
                }
        }
    }

    const int g = lane >> 2, tg = lane & 3;
    if (!SYM) {
#pragma unroll
        for (int mi = 0; mi < 2; mi++)
#pragma unroll
            for (int nj = 0; nj < 8; nj++) {
                int m0 = bm + wm + mi * 16 + g;
                int n0 = bn + wn + nj * 8 + tg * 2;
                float v0 = c[mi][nj][0], v1 = c[mi][nj][1];
                float v2 = c[mi][nj][2], v3 = c[mi][nj][3];
                if (bias) {
                    float b0 = __ldg(&bias[n0]), b1 = __ldg(&bias[n0 + 1]);
                    v0 += b0; v1 += b1; v2 += b0; v3 += b1;
                }
                if (Ch) {
                    __half2 h0 = __floats2half2_rn(v0, v1);
                    __half2 h1 = __floats2half2_rn(v2, v3);
                    if (m0 < M)
                        *(__half2*)(Ch + (size_t)m0 * ldc + n0) = h0;
                    if (m0 + 8 < M)
                        *(__half2*)(Ch + (size_t)(m0 + 8) * ldc + n0) = h1;
                } else {
                    if (m0 < M)
                        *(float2*)&C[(size_t)m0 * ldc + n0] = make_float2(v0, v1);
                    if (m0 + 8 < M)
                        *(float2*)&C[(size_t)(m0 + 8) * ldc + n0] = make_float2(v2, v3);
                }
            }
    } else {
        cpa_wait<0>();
        __syncthreads();
        const int LD = 129;
#pragma unroll
        for (int mi = 0; mi < 2; mi++)
#pragma unroll
            for (int nj = 0; nj < 8; nj++) {
                int r0 = wm + mi * 16 + g;
                int c0 = wn + nj * 8 + tg * 2;
                smf[r0 * LD + c0]       = c[mi][nj][0];
                smf[r0 * LD + c0 + 1]   = c[mi][nj][1];
                smf[(r0 + 8) * LD + c0]     = c[mi][nj][2];
                smf[(r0 + 8) * LD + c0 + 1] = c[mi][nj][3];
            }
        __syncthreads();
#pragma unroll
        for (int it = 0; it < 16; it++) {
            int idx = it * 256 + tid;
            int r = idx >> 5, c4 = (idx & 31) * 4;
            float4 v = make_float4(smf[r * LD + c4], smf[r * LD + c4 + 1],
                                   smf[r * LD + c4 + 2], smf[r * LD + c4 + 3]);
            *(float4*)&C[(size_t)(bm + r) * ldc + bn + c4] = v;
        }
        if (bm != bn) {
#pragma unroll 4
            for (int it = 0; it < 64; it++) {
                int idx = it * 256 + tid;
                int r = idx >> 7, cc = idx & 127;
                C[(size_t)(bn + r) * ldc + bm + cc] = smf[cc * LD + r];
            }
        }
    }
}

// ------------- warp-per-row SpMM: shfl-broadcast edges, no smem/barriers -----------
// Each warp owns one output row. Lane l accumulates cols [4l..4l+3] and [128+4l..+3].
template <bool RELU>
__global__ void __launch_bounds__(256) k_spmm_warp(
    const __half* __restrict__ sup, const float* __restrict__ bias,
    __half* __restrict__ out, const int* __restrict__ rows, int nrows)
{
    const int w = (blockIdx.x * blockDim.x + threadIdx.x) >> 5;
    const int lane = threadIdx.x & 31;
    if (w >= nrows) return;
    const int r = rows ? rows[w] : w;
    const int beg = g_rowptr[r];
    const int end = g_rowptr[r + 1];

    float a0 = 0.f, a1 = 0.f, a2 = 0.f, a3 = 0.f;
    float a4 = 0.f, a5 = 0.f, a6 = 0.f, a7 = 0.f;

    for (int base = beg; base < end; base += 32) {
        const int m = min(32, end - base);
        int   ci = 0;
        float wi = 0.f;
        if (lane < m) {
            ci = g_ecol[base + lane];
            wi = g_ew[base + lane];
        }
        for (int e = 0; e < m; e++) {
            const int   ce = __shfl_sync(0xFFFFFFFFu, ci, e);
            const float we = __shfl_sync(0xFFFFFFFFu, wi, e);
            const uint2* rp = (const uint2*)sup + (size_t)ce * 64;
            uint2 u0 = __ldg(rp + lane);
            uint2 u1 = __ldg(rp + 32 + lane);
            float2 f0 = __half22float2(*(__half2*)&u0.x);
            float2 f1 = __half22float2(*(__half2*)&u0.y);
            float2 f2 = __half22float2(*(__half2*)&u1.x);
            float2 f3 = __half22float2(*(__half2*)&u1.y);
            a0 += we * f0.x; a1 += we * f0.y; a2 += we * f1.x; a3 += we * f1.y;
            a4 += we * f2.x; a5 += we * f2.y; a6 += we * f3.x; a7 += we * f3.y;
        }
    }
    if (bias) {
        float4 b0 = *(const float4*)(bias + 4 * lane);
        float4 b1 = *(const float4*)(bias + 128 + 4 * lane);
        a0 += b0.x; a1 += b0.y; a2 += b0.z; a3 += b0.w;
        a4 += b1.x; a5 += b1.y; a6 += b1.z; a7 += b1.w;
    }
    if (RELU) {
        a0 = fmaxf(a0, 0.f); a1 = fmaxf(a1, 0.f); a2 = fmaxf(a2, 0.f); a3 = fmaxf(a3, 0.f);
        a4 = fmaxf(a4, 0.f); a5 = fmaxf(a5, 0.f); a6 = fmaxf(a6, 0.f); a7 = fmaxf(a7, 0.f);
    }
    __half2 h0 = __floats2half2_rn(a0, a1);
    __half2 h1 = __floats2half2_rn(a2, a3);
    __half2 h2 = __floats2half2_rn(a4, a5);
    __half2 h3 = __floats2half2_rn(a6, a7);
    uint2 o0, o1;
    o0.x = *(uint32_t*)&h0; o0.y = *(uint32_t*)&h1;
    o1.x = *(uint32_t*)&h2; o1.y = *(uint32_t*)&h3;
    uint2* op = (uint2*)out + (size_t)w * 64;
    op[lane] = o0;
    op[32 + lane] = o1;
}

// ---------------- launch ----------------
extern "C" void kernel_launch(void* const* d_in, const int* in_sizes, int n_in,
                              void* d_out, int out_size) {
    const float* X      = (const float*)d_in[0];
    const int*   erow   = (const int*)d_in[1];
    const int*   ecol   = (const int*)d_in[2];
    const float* ew     = (const float*)d_in[3];
    const int*   labels = (const int*)d_in[4];
    const float* W1     = (const float*)d_in[5];
    const float* b1     = (const float*)d_in[6];
    const float* W2     = (const float*)d_in[7];
    const float* b2     = (const float*)d_in[8];
    const float* Wsd    = (const float*)d_in[9];
    const float* bsd    = (const float*)d_in[10];
    float* out = (float*)d_out;

    void *p_sup512, *p_agg, *p_xh, *p_s, *p_wt, *p_idx;
    cudaGetSymbolAddress(&p_sup512, g_sup512);
    cudaGetSymbolAddress(&p_agg, g_agg);
    cudaGetSymbolAddress(&p_xh, g_xh);
    cudaGetSymbolAddress(&p_s, g_s);
    cudaGetSymbolAddress(&p_wt, g_wt);
    cudaGetSymbolAddress(&p_idx, g_idx);
    __half* suph = (__half*)p_sup512;                       // [20000,256]
    __half* axs  = suph + (size_t)NNODES * DIM;             // [4096,256]
    __half* ahs  = axs + (size_t)KSEL * DIM;                // [4096,256]
    __half* h    = (__half*)p_agg;                          // [20000,256]
    __half* xh   = (__half*)p_xh;
    __half* sbuf = (__half*)p_s;                            // [4096,256]
    __half* wt1  = (__half*)p_wt;
    __half* wtsd = (__half*)p_wt + DIM * DIM;
    __half* wt2  = (__half*)p_wt + 2 * DIM * DIM;
    const int* idxp = (const int*)p_idx;

    static cudaStream_t sB = nullptr;
    static cudaEvent_t evFork, evPre, evCsr, evGram;
    if (!sB) {
        cudaFuncSetAttribute(k_gemm_tc<false>,
                             cudaFuncAttributeMaxDynamicSharedMemorySize, GEMM_SMEM);
        cudaFuncSetAttribute(k_gemm_tc<true>,
                             cudaFuncAttributeMaxDynamicSharedMemorySize, GEMM_SMEM);
        cudaStreamCreateWithFlags(&sB, cudaStreamNonBlocking);
        cudaEventCreateWithFlags(&evFork, cudaEventDisableTiming);
        cudaEventCreateWithFlags(&evPre, cudaEventDisableTiming);
        cudaEventCreateWithFlags(&evCsr, cudaEventDisableTiming);
        cudaEventCreateWithFlags(&evGram, cudaEventDisableTiming);
    }

    dim3 g1(DIM / BN, (NNODES + BM - 1) / BM);       // (2, 157)
    dim3 gSmall(DIM / BN, KSEL / BM);                // (2, 32)
    const int gramTiles = (KSEL / BM) * (KSEL / BM + 1) / 2;   // 528
    const int spmmFull = (NNODES * 32 + 255) / 256;  // 2500 blocks
    const int spmmSel  = (KSEL * 32 + 255) / 256;    // 512 blocks

    // fork B at entry: CSR build
    cudaEventRecord(evFork, 0);
    cudaStreamWaitEvent(sB, evFork, 0);

    // --- A: preproc (launch 1) ---
    k_preproc<<<192 + NNODES * DIM / 4 / 256, 256>>>(X, W1, Wsd, W2);
    cudaEventRecord(evPre, 0);

    k_zero_cnt<<<(NNODES + 255) / 256, 256, 0, sB>>>();
    k_hist<<<(NEDGES + 255) / 256, 256, 0, sB>>>(erow);

    // --- A: GEMM1 [20000,256] = xh @ W1t -> suph (launch 4 -> profiled slot) ---
    k_gemm_tc<false><<<g1, 256, GEMM_SMEM>>>(xh, wt1, nullptr, NNODES, DIM,
                                             nullptr, suph);

    k_scan_idx<<<1, 1024, 0, sB>>>(labels);
    k_scatter<<<(NEDGES + 255) / 256, 256, 0, sB>>>(erow, ecol, ew);
    cudaEventRecord(evCsr, sB);

    // --- B: structure chain (CSR + xh) ---
    cudaStreamWaitEvent(sB, evPre, 0);
    k_spmm_warp<false><<<spmmSel, 256, 0, sB>>>(xh, nullptr, axs, idxp, KSEL);
    k_gemm_tc<false><<<gSmall, 256, GEMM_SMEM, sB>>>(
        axs, wtsd, nullptr, KSEL, DIM, bsd, sbuf);                     // s (half)
    k_gemm_tc<true><<<gramTiles, 256, GEMM_SMEM, sB>>>(
        sbuf, sbuf, out + (size_t)KSEL * DIM, KSEL, KSEL, nullptr, nullptr);
    cudaEventRecord(evGram, sB);

    // --- A: attr chain ---
    cudaStreamWaitEvent(0, evCsr, 0);
    k_spmm_warp<true><<<spmmFull, 256>>>(suph, b1, h, nullptr, NNODES);
    k_spmm_warp<false><<<spmmSel, 256>>>(h, nullptr, ahs, idxp, KSEL);
    k_gemm_tc<false><<<gSmall, 256, GEMM_SMEM>>>(
        ahs, wt2, out, KSEL, DIM, b2, nullptr);                        // attr out

    cudaStreamWaitEvent(0, evGram, 0);
}